// round 1
// baseline (speedup 1.0000x reference)
#include <cuda_runtime.h>

#define NN 50000
#define EE 1600000
#define FULL 0xffffffffu

// ---------------- scratch (device globals; no allocation allowed) ----------
__device__ float g_q1[NN*128];
__device__ float g_k1[NN*128];
__device__ float g_v1[NN*128];
__device__ float g_h [NN*128];   // skip (x@Ws1+bs1), later overwritten with relu(layer1 out)
__device__ float g_t1[NN*256];   // t1[n,h,d] = sum_c We1[d,h*32+c] * q1[n,h,c]
__device__ float g_q2[NN*64];
__device__ float g_k2[NN*64];
__device__ float g_v2[NN*64];
__device__ float g_s2[NN*64];
__device__ float g_t2[NN*64];    // t2[n,d] = sum_c We2[d,c] * q2[n,c]
__device__ int   g_cnt[NN];
__device__ int   g_rowptr[NN+1];
__device__ int   g_woff[NN];
__device__ int2  g_edges[EE];    // sorted by dst: {src, original edge id}

// ---------------- CSR build ------------------------------------------------
__global__ void k_zero_cnt() {
    int i = blockIdx.x*blockDim.x + threadIdx.x;
    if (i < NN) g_cnt[i] = 0;
}

__global__ void k_hist(const int* __restrict__ dst) {
    int e = blockIdx.x*blockDim.x + threadIdx.x;
    if (e < EE) atomicAdd(&g_cnt[dst[e]], 1);
}

__global__ void k_scan() {
    __shared__ int s[1024];
    __shared__ int carry;
    if (threadIdx.x == 0) carry = 0;
    __syncthreads();
    for (int base = 0; base < NN; base += 1024) {
        int i = base + threadIdx.x;
        int v = (i < NN) ? g_cnt[i] : 0;
        s[threadIdx.x] = v;
        __syncthreads();
        for (int off = 1; off < 1024; off <<= 1) {
            int t = (threadIdx.x >= off) ? s[threadIdx.x - off] : 0;
            __syncthreads();
            s[threadIdx.x] += t;
            __syncthreads();
        }
        int excl = s[threadIdx.x] - v;
        if (i < NN) { g_rowptr[i] = carry + excl; g_woff[i] = carry + excl; }
        int tot = s[1023];
        __syncthreads();
        if (threadIdx.x == 0) carry += tot;
        __syncthreads();
    }
    if (threadIdx.x == 0) g_rowptr[NN] = carry;
}

__global__ void k_scatter(const int* __restrict__ src, const int* __restrict__ dst) {
    int e = blockIdx.x*blockDim.x + threadIdx.x;
    if (e < EE) {
        int d = dst[e];
        int p = atomicAdd(&g_woff[d], 1);
        g_edges[p] = make_int2(src[e], e);
    }
}

// ---------------- node linear layers ---------------------------------------
// layer 1: 4 matrices [128,128], outputs to globals. BN nodes per block.
__global__ void k_node1(const float* __restrict__ x,
    const float* __restrict__ Wq, const float* __restrict__ bq,
    const float* __restrict__ Wk, const float* __restrict__ bk,
    const float* __restrict__ Wv, const float* __restrict__ bv,
    const float* __restrict__ Ws, const float* __restrict__ bs)
{
    const int CIN = 128, COUT = 128, BN = 16;
    int mat = blockIdx.y;
    const float* W = (mat==0)?Wq:((mat==1)?Wk:((mat==2)?Wv:Ws));
    const float* b = (mat==0)?bq:((mat==1)?bk:((mat==2)?bv:bs));
    float* o = (mat==0)?g_q1:((mat==1)?g_k1:((mat==2)?g_v1:g_h));
    int n0 = blockIdx.x * BN;

    __shared__ float xs[CIN][BN];
    for (int i = threadIdx.x; i < BN*CIN; i += COUT) {
        int nn = i / CIN, c = i % CIN;    // c == threadIdx.x pattern -> coalesced
        xs[c][nn] = x[(size_t)(n0+nn)*CIN + c];
    }
    __syncthreads();

    int col = threadIdx.x;
    float bb = b[col];
    float acc[BN];
    #pragma unroll
    for (int i = 0; i < BN; i++) acc[i] = bb;

    #pragma unroll 2
    for (int k = 0; k < CIN; k++) {
        float wv = W[(size_t)k*COUT + col];
        const float4* xr = (const float4*)xs[k];
        float4 x0 = xr[0], x1 = xr[1], x2 = xr[2], x3 = xr[3];
        acc[0]  += x0.x*wv; acc[1]  += x0.y*wv; acc[2]  += x0.z*wv; acc[3]  += x0.w*wv;
        acc[4]  += x1.x*wv; acc[5]  += x1.y*wv; acc[6]  += x1.z*wv; acc[7]  += x1.w*wv;
        acc[8]  += x2.x*wv; acc[9]  += x2.y*wv; acc[10] += x2.z*wv; acc[11] += x2.w*wv;
        acc[12] += x3.x*wv; acc[13] += x3.y*wv; acc[14] += x3.z*wv; acc[15] += x3.w*wv;
    }
    #pragma unroll
    for (int i = 0; i < BN; i++) o[(size_t)(n0+i)*COUT + col] = acc[i];
}

// layer 2: 4 matrices [128,64], input from g_h.
__global__ void k_node2(
    const float* __restrict__ Wq, const float* __restrict__ bq,
    const float* __restrict__ Wk, const float* __restrict__ bk,
    const float* __restrict__ Wv, const float* __restrict__ bv,
    const float* __restrict__ Ws, const float* __restrict__ bs)
{
    const int CIN = 128, COUT = 64, BN = 16;
    int mat = blockIdx.y;
    const float* W = (mat==0)?Wq:((mat==1)?Wk:((mat==2)?Wv:Ws));
    const float* b = (mat==0)?bq:((mat==1)?bk:((mat==2)?bv:bs));
    float* o = (mat==0)?g_q2:((mat==1)?g_k2:((mat==2)?g_v2:g_s2));
    int n0 = blockIdx.x * BN;

    __shared__ float xs[CIN][BN];
    for (int i = threadIdx.x; i < BN*CIN; i += COUT) {
        int nn = i / CIN, c = i % CIN;
        xs[c][nn] = g_h[(size_t)(n0+nn)*CIN + c];
    }
    __syncthreads();

    int col = threadIdx.x;
    float bb = b[col];
    float acc[BN];
    #pragma unroll
    for (int i = 0; i < BN; i++) acc[i] = bb;

    #pragma unroll 2
    for (int k = 0; k < CIN; k++) {
        float wv = W[(size_t)k*COUT + col];
        const float4* xr = (const float4*)xs[k];
        float4 x0 = xr[0], x1 = xr[1], x2 = xr[2], x3 = xr[3];
        acc[0]  += x0.x*wv; acc[1]  += x0.y*wv; acc[2]  += x0.z*wv; acc[3]  += x0.w*wv;
        acc[4]  += x1.x*wv; acc[5]  += x1.y*wv; acc[6]  += x1.z*wv; acc[7]  += x1.w*wv;
        acc[8]  += x2.x*wv; acc[9]  += x2.y*wv; acc[10] += x2.z*wv; acc[11] += x2.w*wv;
        acc[12] += x3.x*wv; acc[13] += x3.y*wv; acc[14] += x3.z*wv; acc[15] += x3.w*wv;
    }
    #pragma unroll
    for (int i = 0; i < BN; i++) o[(size_t)(n0+i)*COUT + col] = acc[i];
}

// ---------------- t tables --------------------------------------------------
__global__ void k_t1(const float* __restrict__ We1) {
    int n = blockIdx.x;
    int t = threadIdx.x;           // 256 threads
    __shared__ float q[128];
    if (t < 128) q[t] = g_q1[(size_t)n*128 + t];
    __syncthreads();
    int h = t >> 6, d = t & 63;
    const float* wp = We1 + (size_t)d*128 + h*32;
    const float* qp = q + h*32;
    float acc = 0.f;
    #pragma unroll
    for (int c = 0; c < 32; c++) acc += wp[c] * qp[c];
    g_t1[(size_t)n*256 + t] = acc;
}

__global__ void k_t2(const float* __restrict__ We2) {
    int idx = blockIdx.x*256 + threadIdx.x;
    int n = idx >> 6, d = idx & 63;
    if (n >= NN) return;
    __shared__ float q[4][64];
    int ln = threadIdx.x >> 6;
    q[ln][d] = g_q2[(size_t)n*64 + d];
    __syncthreads();
    const float* wp = We2 + (size_t)d*64;
    float acc = 0.f;
    #pragma unroll
    for (int c = 0; c < 64; c++) acc += wp[c] * q[ln][c];
    g_t2[(size_t)n*64 + d] = acc;
}

// ---------------- attention layer 1 (H=4, C=32), warp per dst node ---------
__global__ void k_attn1(const float* __restrict__ ef, const float* __restrict__ We1) {
    int lane = threadIdx.x & 31;
    int wl   = threadIdx.x >> 5;
    int n    = blockIdx.x*8 + wl;
    __shared__ float smemAll[8*640];
    float* qs  = smemAll + wl*640;   // 128
    float* ts  = qs + 128;           // 256
    float* aux = qs + 384;           // 256 (stash during loop, g at end)
    if (n >= NN) return;

    {
        const float4* qsrc = (const float4*)(g_q1 + (size_t)n*128);
        ((float4*)qs)[lane] = qsrc[lane];
        const float4* tsrc = (const float4*)(g_t1 + (size_t)n*256);
        ((float4*)ts)[lane]      = tsrc[lane];
        ((float4*)ts)[lane + 32] = tsrc[lane + 32];
    }
    __syncwarp();

    float4 accv  = make_float4(0.f,0.f,0.f,0.f);
    float4 accg0 = make_float4(0.f,0.f,0.f,0.f);
    float4 accg1 = make_float4(0.f,0.f,0.f,0.f);
    float den[4] = {0.f,0.f,0.f,0.f};

    int rs = g_rowptr[n], re = g_rowptr[n+1];
    const float inv_s = 0.1767766952966369f;   // 1/sqrt(32)
    int hh  = lane >> 3;
    int efo = (lane*8) & 63;

    for (int base = rs; base < re; base += 32) {
        int cnt = min(32, re - base);
        float w[4] = {0.f,0.f,0.f,0.f};
        int src = 0, eid = 0;
        if (lane < cnt) {
            int2 se = g_edges[base + lane];
            src = se.x; eid = se.y;
            float a[4] = {0.f,0.f,0.f,0.f};
            const float4* kp = (const float4*)(g_k1 + (size_t)src*128);
            #pragma unroll
            for (int h2 = 0; h2 < 4; h2++) {
                #pragma unroll
                for (int i = 0; i < 8; i++) {
                    float4 kv = kp[h2*8 + i];
                    const float* qh = qs + h2*32 + i*4;
                    a[h2] += kv.x*qh[0] + kv.y*qh[1] + kv.z*qh[2] + kv.w*qh[3];
                }
            }
            const float4* ep = (const float4*)(ef + (size_t)eid*64);
            #pragma unroll
            for (int i = 0; i < 16; i++) {
                float4 ev = ep[i];
                #pragma unroll
                for (int h2 = 0; h2 < 4; h2++) {
                    const float* th = ts + h2*64 + i*4;
                    a[h2] += ev.x*th[0] + ev.y*th[1] + ev.z*th[2] + ev.w*th[3];
                }
            }
            #pragma unroll
            for (int h2 = 0; h2 < 4; h2++) { w[h2] = __expf(a[h2]*inv_s); den[h2] += w[h2]; }
        }
        float* ax = aux + lane*6;
        ax[0] = w[0]; ax[1] = w[1]; ax[2] = w[2]; ax[3] = w[3];
        ax[4] = __int_as_float(src); ax[5] = __int_as_float(eid);
        __syncwarp();
        #pragma unroll 2
        for (int jj = 0; jj < cnt; jj++) {
            const float* aj = aux + jj*6;
            float wh  = aj[hh];
            int  srcj = __float_as_int(aj[4]);
            int  eidj = __float_as_int(aj[5]);
            float4 vv = *(const float4*)(g_v1 + (size_t)srcj*128 + lane*4);
            accv.x += wh*vv.x; accv.y += wh*vv.y; accv.z += wh*vv.z; accv.w += wh*vv.w;
            const float* ee = ef + (size_t)eidj*64 + efo;
            float4 e0 = *(const float4*)ee;
            float4 e1 = *(const float4*)(ee + 4);
            accg0.x += wh*e0.x; accg0.y += wh*e0.y; accg0.z += wh*e0.z; accg0.w += wh*e0.w;
            accg1.x += wh*e1.x; accg1.y += wh*e1.y; accg1.z += wh*e1.z; accg1.w += wh*e1.w;
        }
        __syncwarp();
    }

    #pragma unroll
    for (int h2 = 0; h2 < 4; h2++) {
        #pragma unroll
        for (int o = 16; o; o >>= 1) den[h2] += __shfl_xor_sync(FULL, den[h2], o);
    }
    float denh = (hh==0)?den[0]:((hh==1)?den[1]:((hh==2)?den[2]:den[3]));

    float* gs = aux;
    *(float4*)(gs + lane*8)     = accg0;
    *(float4*)(gs + lane*8 + 4) = accg1;
    __syncwarp();

    float4 og = make_float4(0.f,0.f,0.f,0.f);
    const float* Wc = We1 + hh*32 + (lane & 7)*4;   // column block == channels lane*4..+3
    const float* gh = gs + hh*64;
    #pragma unroll 8
    for (int d = 0; d < 64; d++) {
        float g = gh[d];
        float4 wr = *(const float4*)(Wc + (size_t)d*128);
        og.x += g*wr.x; og.y += g*wr.y; og.z += g*wr.z; og.w += g*wr.w;
    }
    float inv = (denh > 0.f) ? (1.f/denh) : 0.f;
    float4 skip = *(const float4*)(g_h + (size_t)n*128 + lane*4);
    float4 o;
    o.x = fmaxf(fmaf(accv.x + og.x, inv, skip.x), 0.f);
    o.y = fmaxf(fmaf(accv.y + og.y, inv, skip.y), 0.f);
    o.z = fmaxf(fmaf(accv.z + og.z, inv, skip.z), 0.f);
    o.w = fmaxf(fmaf(accv.w + og.w, inv, skip.w), 0.f);
    *(float4*)(g_h + (size_t)n*128 + lane*4) = o;
}

// ---------------- attention layer 2 (H=1, C=64), warp per dst node ---------
__global__ void k_attn2(const float* __restrict__ ef, const float* __restrict__ We2,
                        float* __restrict__ out) {
    int lane = threadIdx.x & 31;
    int wl   = threadIdx.x >> 5;
    int n    = blockIdx.x*8 + wl;
    __shared__ float smemAll[8*224];
    float* qs  = smemAll + wl*224;  // 64
    float* ts  = qs + 64;           // 64
    float* aux = qs + 128;          // 96
    if (n >= NN) return;

    ((float2*)qs)[lane] = ((const float2*)(g_q2 + (size_t)n*64))[lane];
    ((float2*)ts)[lane] = ((const float2*)(g_t2 + (size_t)n*64))[lane];
    __syncwarp();

    float2 accv = make_float2(0.f,0.f);
    float2 accg = make_float2(0.f,0.f);
    float den = 0.f;
    int rs = g_rowptr[n], re = g_rowptr[n+1];

    for (int base = rs; base < re; base += 32) {
        int cnt = min(32, re - base);
        float w = 0.f; int src = 0, eid = 0;
        if (lane < cnt) {
            int2 se = g_edges[base + lane];
            src = se.x; eid = se.y;
            float a = 0.f;
            const float4* kp = (const float4*)(g_k2 + (size_t)src*64);
            const float4* ep = (const float4*)(ef + (size_t)eid*64);
            #pragma unroll
            for (int i = 0; i < 16; i++) {
                float4 kv = kp[i]; const float* qh = qs + i*4;
                a += kv.x*qh[0] + kv.y*qh[1] + kv.z*qh[2] + kv.w*qh[3];
                float4 ev = ep[i]; const float* th = ts + i*4;
                a += ev.x*th[0] + ev.y*th[1] + ev.z*th[2] + ev.w*th[3];
            }
            w = __expf(a*0.125f);   // 1/sqrt(64)
            den += w;
        }
        float* ax = aux + lane*3;
        ax[0] = w; ax[1] = __int_as_float(src); ax[2] = __int_as_float(eid);
        __syncwarp();
        #pragma unroll 2
        for (int jj = 0; jj < cnt; jj++) {
            const float* aj = aux + jj*3;
            float wh  = aj[0];
            int  srcj = __float_as_int(aj[1]);
            int  eidj = __float_as_int(aj[2]);
            float2 vv = *(const float2*)(g_v2 + (size_t)srcj*64 + lane*2);
            float2 ee = *(const float2*)(ef + (size_t)eidj*64 + lane*2);
            accv.x += wh*vv.x; accv.y += wh*vv.y;
            accg.x += wh*ee.x; accg.y += wh*ee.y;
        }
        __syncwarp();
    }

    #pragma unroll
    for (int o = 16; o; o >>= 1) den += __shfl_xor_sync(FULL, den, o);

    float* gs = aux;
    *(float2*)(gs + lane*2) = accg;
    __syncwarp();

    float2 og = make_float2(0.f,0.f);
    const float* Wc = We2 + lane*2;
    #pragma unroll 8
    for (int d = 0; d < 64; d++) {
        float g = gs[d];
        float2 wr = *(const float2*)(Wc + (size_t)d*64);
        og.x += g*wr.x; og.y += g*wr.y;
    }
    float inv = (den > 0.f) ? (1.f/den) : 0.f;
    float2 s2 = *(const float2*)(g_s2 + (size_t)n*64 + lane*2);
    float2 o;
    o.x = fmaf(accv.x + og.x, inv, s2.x);
    o.y = fmaf(accv.y + og.y, inv, s2.y);
    *(float2*)(out + (size_t)n*64 + lane*2) = o;
}

// ---------------- launch -----------------------------------------------------
extern "C" void kernel_launch(void* const* d_in, const int* in_sizes, int n_in,
                              void* d_out, int out_size)
{
    const float* x   = (const float*)d_in[0];
    const float* ef  = (const float*)d_in[1];
    const int*   ei  = (const int*)  d_in[2];
    const float *Wq1 = (const float*)d_in[3],  *bq1 = (const float*)d_in[4];
    const float *Wk1 = (const float*)d_in[5],  *bk1 = (const float*)d_in[6];
    const float *Wv1 = (const float*)d_in[7],  *bv1 = (const float*)d_in[8];
    const float *We1 = (const float*)d_in[9];
    const float *Ws1 = (const float*)d_in[10], *bs1 = (const float*)d_in[11];
    const float *Wq2 = (const float*)d_in[12], *bq2 = (const float*)d_in[13];
    const float *Wk2 = (const float*)d_in[14], *bk2 = (const float*)d_in[15];
    const float *Wv2 = (const float*)d_in[16], *bv2 = (const float*)d_in[17];
    const float *We2 = (const float*)d_in[18];
    const float *Ws2 = (const float*)d_in[19], *bs2 = (const float*)d_in[20];
    float* out = (float*)d_out;

    const int* srcp = ei;        // edge_index[0]
    const int* dstp = ei + EE;   // edge_index[1]

    // CSR by dst (rebuilt every call; deterministic up to fp-sum order)
    k_zero_cnt<<<(NN+255)/256, 256>>>();
    k_hist   <<<(EE+255)/256, 256>>>(dstp);
    k_scan   <<<1, 1024>>>();
    k_scatter<<<(EE+255)/256, 256>>>(srcp, dstp);

    // layer 1
    dim3 g1(NN/16, 4);
    k_node1<<<g1, 128>>>(x, Wq1,bq1, Wk1,bk1, Wv1,bv1, Ws1,bs1);
    k_t1   <<<NN, 256>>>(We1);
    k_attn1<<<(NN+7)/8, 256>>>(ef, We1);

    // layer 2
    k_node2<<<g1, 64>>>(Wq2,bq2, Wk2,bk2, Wv2,bv2, Ws2,bs2);
    k_t2   <<<NN/4, 256>>>(We2);
    k_attn2<<<(NN+7)/8, 256>>>(ef, We2, out);
}

// round 2
// speedup vs baseline: 2.6146x; 2.6146x over previous
#include <cuda_runtime.h>

#define NN 50000
#define EE 1600000
#define FULL 0xffffffffu

// ---------------- scratch (device globals; no allocation allowed) ----------
__device__ float g_q1[NN*128];
__device__ float g_k1[NN*128];
__device__ float g_v1[NN*128];
__device__ float g_h [NN*128];   // skip (x@Ws1+bs1), later relu(layer1 out)
__device__ float g_t1[NN*256];   // t1[n,h,d] = sum_c We1[d,h*32+c] * q1[n,h,c]
__device__ float g_q2[NN*64];
__device__ float g_k2[NN*64];
__device__ float g_v2[NN*64];
__device__ float g_s2[NN*64];
__device__ float g_t2[NN*64];    // t2[n,d] = sum_c We2[d,c] * q2[n,c]
__device__ int   g_cnt[NN];
__device__ int   g_rowptr[NN+1];
__device__ int   g_woff[NN];
__device__ int2  g_edges[EE];    // sorted by dst: {src, original edge id}

// ---------------- CSR build ------------------------------------------------
__global__ void k_zero_cnt() {
    int i = blockIdx.x*blockDim.x + threadIdx.x;
    if (i < NN) g_cnt[i] = 0;
}

__global__ void k_hist(const int* __restrict__ dst) {
    int e = blockIdx.x*blockDim.x + threadIdx.x;
    if (e < EE) atomicAdd(&g_cnt[dst[e]], 1);
}

__global__ void k_scan() {
    __shared__ int s[1024];
    __shared__ int carry;
    if (threadIdx.x == 0) carry = 0;
    __syncthreads();
    for (int base = 0; base < NN; base += 1024) {
        int i = base + threadIdx.x;
        int v = (i < NN) ? g_cnt[i] : 0;
        s[threadIdx.x] = v;
        __syncthreads();
        for (int off = 1; off < 1024; off <<= 1) {
            int t = (threadIdx.x >= off) ? s[threadIdx.x - off] : 0;
            __syncthreads();
            s[threadIdx.x] += t;
            __syncthreads();
        }
        int excl = s[threadIdx.x] - v;
        if (i < NN) { g_rowptr[i] = carry + excl; g_woff[i] = carry + excl; }
        int tot = s[1023];
        __syncthreads();
        if (threadIdx.x == 0) carry += tot;
        __syncthreads();
    }
    if (threadIdx.x == 0) g_rowptr[NN] = carry;
}

__global__ void k_scatter(const int* __restrict__ src, const int* __restrict__ dst) {
    int e = blockIdx.x*blockDim.x + threadIdx.x;
    if (e < EE) {
        int d = dst[e];
        int p = atomicAdd(&g_woff[d], 1);
        g_edges[p] = make_int2(src[e], e);
    }
}

// ---------------- node linear layers ---------------------------------------
__global__ void k_node1(const float* __restrict__ x,
    const float* __restrict__ Wq, const float* __restrict__ bq,
    const float* __restrict__ Wk, const float* __restrict__ bk,
    const float* __restrict__ Wv, const float* __restrict__ bv,
    const float* __restrict__ Ws, const float* __restrict__ bs)
{
    const int CIN = 128, COUT = 128, BN = 16;
    int mat = blockIdx.y;
    const float* W = (mat==0)?Wq:((mat==1)?Wk:((mat==2)?Wv:Ws));
    const float* b = (mat==0)?bq:((mat==1)?bk:((mat==2)?bv:bs));
    float* o = (mat==0)?g_q1:((mat==1)?g_k1:((mat==2)?g_v1:g_h));
    int n0 = blockIdx.x * BN;

    __shared__ float xs[CIN][BN];
    for (int i = threadIdx.x; i < BN*CIN; i += COUT) {
        int nn = i / CIN, c = i % CIN;
        xs[c][nn] = x[(size_t)(n0+nn)*CIN + c];
    }
    __syncthreads();

    int col = threadIdx.x;
    float bb = b[col];
    float acc[BN];
    #pragma unroll
    for (int i = 0; i < BN; i++) acc[i] = bb;

    #pragma unroll 2
    for (int k = 0; k < CIN; k++) {
        float wv = W[(size_t)k*COUT + col];
        const float4* xr = (const float4*)xs[k];
        float4 x0 = xr[0], x1 = xr[1], x2 = xr[2], x3 = xr[3];
        acc[0]  += x0.x*wv; acc[1]  += x0.y*wv; acc[2]  += x0.z*wv; acc[3]  += x0.w*wv;
        acc[4]  += x1.x*wv; acc[5]  += x1.y*wv; acc[6]  += x1.z*wv; acc[7]  += x1.w*wv;
        acc[8]  += x2.x*wv; acc[9]  += x2.y*wv; acc[10] += x2.z*wv; acc[11] += x2.w*wv;
        acc[12] += x3.x*wv; acc[13] += x3.y*wv; acc[14] += x3.z*wv; acc[15] += x3.w*wv;
    }
    #pragma unroll
    for (int i = 0; i < BN; i++) o[(size_t)(n0+i)*COUT + col] = acc[i];
}

__global__ void k_node2(
    const float* __restrict__ Wq, const float* __restrict__ bq,
    const float* __restrict__ Wk, const float* __restrict__ bk,
    const float* __restrict__ Wv, const float* __restrict__ bv,
    const float* __restrict__ Ws, const float* __restrict__ bs)
{
    const int CIN = 128, COUT = 64, BN = 16;
    int mat = blockIdx.y;
    const float* W = (mat==0)?Wq:((mat==1)?Wk:((mat==2)?Wv:Ws));
    const float* b = (mat==0)?bq:((mat==1)?bk:((mat==2)?bv:bs));
    float* o = (mat==0)?g_q2:((mat==1)?g_k2:((mat==2)?g_v2:g_s2));
    int n0 = blockIdx.x * BN;

    __shared__ float xs[CIN][BN];
    for (int i = threadIdx.x; i < BN*CIN; i += COUT) {
        int nn = i / CIN, c = i % CIN;
        xs[c][nn] = g_h[(size_t)(n0+nn)*CIN + c];
    }
    __syncthreads();

    int col = threadIdx.x;
    float bb = b[col];
    float acc[BN];
    #pragma unroll
    for (int i = 0; i < BN; i++) acc[i] = bb;

    #pragma unroll 2
    for (int k = 0; k < CIN; k++) {
        float wv = W[(size_t)k*COUT + col];
        const float4* xr = (const float4*)xs[k];
        float4 x0 = xr[0], x1 = xr[1], x2 = xr[2], x3 = xr[3];
        acc[0]  += x0.x*wv; acc[1]  += x0.y*wv; acc[2]  += x0.z*wv; acc[3]  += x0.w*wv;
        acc[4]  += x1.x*wv; acc[5]  += x1.y*wv; acc[6]  += x1.z*wv; acc[7]  += x1.w*wv;
        acc[8]  += x2.x*wv; acc[9]  += x2.y*wv; acc[10] += x2.z*wv; acc[11] += x2.w*wv;
        acc[12] += x3.x*wv; acc[13] += x3.y*wv; acc[14] += x3.z*wv; acc[15] += x3.w*wv;
    }
    #pragma unroll
    for (int i = 0; i < BN; i++) o[(size_t)(n0+i)*COUT + col] = acc[i];
}

// ---------------- t tables (smem-staged, coalesced) -------------------------
// t1[n, h*64+d] = sum_c We1[d*128 + h*32 + c] * q1[n*128 + h*32 + c]
__global__ void k_t1(const float* __restrict__ We1) {
    int h = blockIdx.y;
    __shared__ float Wt[32][65];    // Wt[c][d]
    __shared__ float qsm[32][33];   // qsm[n][c]
    int tid = threadIdx.x;
    for (int i = tid; i < 64*32; i += 256) {
        int d = i >> 5, c = i & 31;
        Wt[c][d] = We1[(size_t)d*128 + h*32 + c];
    }
    int n0 = blockIdx.x * 32;
    for (int i = tid; i < 32*32; i += 256) {
        int nn = i >> 5, c = i & 31;
        qsm[nn][c] = (n0+nn < NN) ? g_q1[(size_t)(n0+nn)*128 + h*32 + c] : 0.f;
    }
    __syncthreads();
    int d = tid & 63, nb = tid >> 6;
    #pragma unroll
    for (int p = 0; p < 8; p++) {
        int nn = p*4 + nb;
        float acc = 0.f;
        #pragma unroll
        for (int c = 0; c < 32; c++) acc += qsm[nn][c] * Wt[c][d];
        if (n0+nn < NN) g_t1[(size_t)(n0+nn)*256 + h*64 + d] = acc;
    }
}

// t2[n, d] = sum_c We2[d*64 + c] * q2[n*64 + c]
__global__ void k_t2(const float* __restrict__ We2) {
    __shared__ float Wt[64][65];
    __shared__ float qsm[32][65];
    int tid = threadIdx.x;
    for (int i = tid; i < 64*64; i += 256) {
        int d = i >> 6, c = i & 63;
        Wt[c][d] = We2[(size_t)d*64 + c];
    }
    int n0 = blockIdx.x * 32;
    for (int i = tid; i < 32*64; i += 256) {
        int nn = i >> 6, c = i & 63;
        qsm[nn][c] = (n0+nn < NN) ? g_q2[(size_t)(n0+nn)*64 + c] : 0.f;
    }
    __syncthreads();
    int d = tid & 63, nb = tid >> 6;
    #pragma unroll
    for (int p = 0; p < 8; p++) {
        int nn = p*4 + nb;
        float acc = 0.f;
        #pragma unroll
        for (int c = 0; c < 64; c++) acc += qsm[nn][c] * Wt[c][d];
        if (n0+nn < NN) g_t2[(size_t)(n0+nn)*64 + d] = acc;
    }
}

// ---------------- attention layer 1 (H=4, C=32), warp per dst node ---------
__global__ void k_attn1(const float* __restrict__ ef, const float* __restrict__ We1) {
    int lane = threadIdx.x & 31;
    int wl   = threadIdx.x >> 5;
    int n    = blockIdx.x*8 + wl;
    __shared__ float smemAll[8*640];
    float* qs  = smemAll + wl*640;   // 128
    float* ts  = qs + 128;           // 256
    float* aux = qs + 384;           // 256 (w/src/eid stash, g at end)
    if (n >= NN) return;

    {
        const float4* qsrc = (const float4*)(g_q1 + (size_t)n*128);
        ((float4*)qs)[lane] = qsrc[lane];
        const float4* tsrc = (const float4*)(g_t1 + (size_t)n*256);
        ((float4*)ts)[lane]      = tsrc[lane];
        ((float4*)ts)[lane + 32] = tsrc[lane + 32];
    }
    __syncwarp();

    float4 accv  = make_float4(0.f,0.f,0.f,0.f);
    float4 accg0 = make_float4(0.f,0.f,0.f,0.f);
    float4 accg1 = make_float4(0.f,0.f,0.f,0.f);
    float den[4] = {0.f,0.f,0.f,0.f};

    int rs = g_rowptr[n], re = g_rowptr[n+1];
    const float inv_s = 0.1767766952966369f;   // 1/sqrt(32)
    int hh  = lane >> 3;
    int l8  = lane & 7;
    int grp = lane >> 3;
    int efo = (lane*8) & 63;

    for (int base = rs; base < re; base += 32) {
        int cnt = min(32, re - base);
        int2 se = make_int2(0, 0);
        if (lane < cnt) se = g_edges[base + lane];
        // stash src/eid (all lanes)
        {
            float* ax = aux + lane*8;
            ax[4] = __int_as_float(se.x);
            ax[5] = __int_as_float(se.y);
        }
        // cooperative score: 4 edges in flight, 8 lanes per edge
        #pragma unroll 2
        for (int sub = 0; sub < 8; sub++) {
            int el = sub*4 + grp;
            int esrc = __shfl_sync(FULL, se.x, el);
            int eeid = __shfl_sync(FULL, se.y, el);
            float acc[4] = {0.f,0.f,0.f,0.f};
            const float4* kp = (const float4*)(g_k1 + (size_t)esrc*128);
            #pragma unroll
            for (int h2 = 0; h2 < 4; h2++) {
                float4 kv = kp[h2*8 + l8];
                const float* qh = qs + h2*32 + l8*4;
                acc[h2] += kv.x*qh[0] + kv.y*qh[1] + kv.z*qh[2] + kv.w*qh[3];
            }
            const float4* ep = (const float4*)(ef + (size_t)eeid*64);
            #pragma unroll
            for (int st = 0; st < 2; st++) {
                float4 ev = ep[st*8 + l8];
                #pragma unroll
                for (int h2 = 0; h2 < 4; h2++) {
                    const float* th = ts + h2*64 + st*32 + l8*4;
                    acc[h2] += ev.x*th[0] + ev.y*th[1] + ev.z*th[2] + ev.w*th[3];
                }
            }
            #pragma unroll
            for (int h2 = 0; h2 < 4; h2++) {
                acc[h2] += __shfl_xor_sync(FULL, acc[h2], 1);
                acc[h2] += __shfl_xor_sync(FULL, acc[h2], 2);
                acc[h2] += __shfl_xor_sync(FULL, acc[h2], 4);
            }
            if (l8 == 0) {
                bool valid = el < cnt;
                float4 w4;
                w4.x = valid ? __expf(acc[0]*inv_s) : 0.f;
                w4.y = valid ? __expf(acc[1]*inv_s) : 0.f;
                w4.z = valid ? __expf(acc[2]*inv_s) : 0.f;
                w4.w = valid ? __expf(acc[3]*inv_s) : 0.f;
                den[0] += w4.x; den[1] += w4.y; den[2] += w4.z; den[3] += w4.w;
                *(float4*)(aux + el*8) = w4;
            }
        }
        __syncwarp();
        // accumulate: whole warp per edge
        #pragma unroll 4
        for (int jj = 0; jj < cnt; jj++) {
            const float* aj = aux + jj*8;
            float wh  = aj[hh];
            int  srcj = __float_as_int(aj[4]);
            int  eidj = __float_as_int(aj[5]);
            float4 vv = *(const float4*)(g_v1 + (size_t)srcj*128 + lane*4);
            accv.x += wh*vv.x; accv.y += wh*vv.y; accv.z += wh*vv.z; accv.w += wh*vv.w;
            const float* ee = ef + (size_t)eidj*64 + efo;
            float4 e0 = *(const float4*)ee;
            float4 e1 = *(const float4*)(ee + 4);
            accg0.x += wh*e0.x; accg0.y += wh*e0.y; accg0.z += wh*e0.z; accg0.w += wh*e0.w;
            accg1.x += wh*e1.x; accg1.y += wh*e1.y; accg1.z += wh*e1.z; accg1.w += wh*e1.w;
        }
        __syncwarp();
    }

    #pragma unroll
    for (int h2 = 0; h2 < 4; h2++) {
        #pragma unroll
        for (int o = 16; o; o >>= 1) den[h2] += __shfl_xor_sync(FULL, den[h2], o);
    }
    float denh = (hh==0)?den[0]:((hh==1)?den[1]:((hh==2)?den[2]:den[3]));

    float* gs = aux;
    *(float4*)(gs + lane*8)     = accg0;
    *(float4*)(gs + lane*8 + 4) = accg1;
    __syncwarp();

    float4 og = make_float4(0.f,0.f,0.f,0.f);
    const float* Wc = We1 + hh*32 + (lane & 7)*4;
    const float* gh = gs + hh*64;
    #pragma unroll 8
    for (int d = 0; d < 64; d++) {
        float g = gh[d];
        float4 wr = *(const float4*)(Wc + (size_t)d*128);
        og.x += g*wr.x; og.y += g*wr.y; og.z += g*wr.z; og.w += g*wr.w;
    }
    float inv = (denh > 0.f) ? (1.f/denh) : 0.f;
    float4 skip = *(const float4*)(g_h + (size_t)n*128 + lane*4);
    float4 o;
    o.x = fmaxf(fmaf(accv.x + og.x, inv, skip.x), 0.f);
    o.y = fmaxf(fmaf(accv.y + og.y, inv, skip.y), 0.f);
    o.z = fmaxf(fmaf(accv.z + og.z, inv, skip.z), 0.f);
    o.w = fmaxf(fmaf(accv.w + og.w, inv, skip.w), 0.f);
    *(float4*)(g_h + (size_t)n*128 + lane*4) = o;
}

// ---------------- attention layer 2 (H=1, C=64), warp per dst node ---------
__global__ void k_attn2(const float* __restrict__ ef, const float* __restrict__ We2,
                        float* __restrict__ out) {
    int lane = threadIdx.x & 31;
    int wl   = threadIdx.x >> 5;
    int n    = blockIdx.x*8 + wl;
    __shared__ float smemAll[8*256];
    float* qs  = smemAll + wl*256;  // 64
    float* ts  = qs + 64;           // 64
    float* aux = qs + 128;          // 128
    if (n >= NN) return;

    ((float2*)qs)[lane] = ((const float2*)(g_q2 + (size_t)n*64))[lane];
    ((float2*)ts)[lane] = ((const float2*)(g_t2 + (size_t)n*64))[lane];
    __syncwarp();

    float2 accv = make_float2(0.f,0.f);
    float2 accg = make_float2(0.f,0.f);
    float den = 0.f;
    int rs = g_rowptr[n], re = g_rowptr[n+1];
    int l8  = lane & 7;
    int grp = lane >> 3;

    for (int base = rs; base < re; base += 32) {
        int cnt = min(32, re - base);
        int2 se = make_int2(0, 0);
        if (lane < cnt) se = g_edges[base + lane];
        {
            float* ax = aux + lane*4;
            ax[1] = __int_as_float(se.x);
            ax[2] = __int_as_float(se.y);
        }
        #pragma unroll 2
        for (int sub = 0; sub < 8; sub++) {
            int el = sub*4 + grp;
            int esrc = __shfl_sync(FULL, se.x, el);
            int eeid = __shfl_sync(FULL, se.y, el);
            float acc = 0.f;
            const float4* kp = (const float4*)(g_k2 + (size_t)esrc*64);
            const float4* ep = (const float4*)(ef + (size_t)eeid*64);
            #pragma unroll
            for (int st = 0; st < 2; st++) {
                float4 kv = kp[st*8 + l8];
                const float* qh = qs + st*32 + l8*4;
                acc += kv.x*qh[0] + kv.y*qh[1] + kv.z*qh[2] + kv.w*qh[3];
                float4 ev = ep[st*8 + l8];
                const float* th = ts + st*32 + l8*4;
                acc += ev.x*th[0] + ev.y*th[1] + ev.z*th[2] + ev.w*th[3];
            }
            acc += __shfl_xor_sync(FULL, acc, 1);
            acc += __shfl_xor_sync(FULL, acc, 2);
            acc += __shfl_xor_sync(FULL, acc, 4);
            if (l8 == 0) {
                float w = (el < cnt) ? __expf(acc*0.125f) : 0.f;
                den += w;
                aux[el*4] = w;
            }
        }
        __syncwarp();
        #pragma unroll 4
        for (int jj = 0; jj < cnt; jj++) {
            const float* aj = aux + jj*4;
            float wh  = aj[0];
            int  srcj = __float_as_int(aj[1]);
            int  eidj = __float_as_int(aj[2]);
            float2 vv = *(const float2*)(g_v2 + (size_t)srcj*64 + lane*2);
            float2 ee = *(const float2*)(ef + (size_t)eidj*64 + lane*2);
            accv.x += wh*vv.x; accv.y += wh*vv.y;
            accg.x += wh*ee.x; accg.y += wh*ee.y;
        }
        __syncwarp();
    }

    #pragma unroll
    for (int o = 16; o; o >>= 1) den += __shfl_xor_sync(FULL, den, o);

    float* gs = aux;
    *(float2*)(gs + lane*2) = accg;
    __syncwarp();

    float2 og = make_float2(0.f,0.f);
    const float* Wc = We2 + lane*2;
    #pragma unroll 8
    for (int d = 0; d < 64; d++) {
        float g = gs[d];
        float2 wr = *(const float2*)(Wc + (size_t)d*64);
        og.x += g*wr.x; og.y += g*wr.y;
    }
    float inv = (den > 0.f) ? (1.f/den) : 0.f;
    float2 s2 = *(const float2*)(g_s2 + (size_t)n*64 + lane*2);
    float2 o;
    o.x = fmaf(accv.x + og.x, inv, s2.x);
    o.y = fmaf(accv.y + og.y, inv, s2.y);
    *(float2*)(out + (size_t)n*64 + lane*2) = o;
}

// ---------------- launch -----------------------------------------------------
extern "C" void kernel_launch(void* const* d_in, const int* in_sizes, int n_in,
                              void* d_out, int out_size)
{
    const float* x   = (const float*)d_in[0];
    const float* ef  = (const float*)d_in[1];
    const int*   ei  = (const int*)  d_in[2];
    const float *Wq1 = (const float*)d_in[3],  *bq1 = (const float*)d_in[4];
    const float *Wk1 = (const float*)d_in[5],  *bk1 = (const float*)d_in[6];
    const float *Wv1 = (const float*)d_in[7],  *bv1 = (const float*)d_in[8];
    const float *We1 = (const float*)d_in[9];
    const float *Ws1 = (const float*)d_in[10], *bs1 = (const float*)d_in[11];
    const float *Wq2 = (const float*)d_in[12], *bq2 = (const float*)d_in[13];
    const float *Wk2 = (const float*)d_in[14], *bk2 = (const float*)d_in[15];
    const float *Wv2 = (const float*)d_in[16], *bv2 = (const float*)d_in[17];
    const float *We2 = (const float*)d_in[18];
    const float *Ws2 = (const float*)d_in[19], *bs2 = (const float*)d_in[20];
    float* out = (float*)d_out;

    const int* srcp = ei;        // edge_index[0]
    const int* dstp = ei + EE;   // edge_index[1]

    // CSR by dst
    k_zero_cnt<<<(NN+255)/256, 256>>>();
    k_hist   <<<(EE+255)/256, 256>>>(dstp);
    k_scan   <<<1, 1024>>>();
    k_scatter<<<(EE+255)/256, 256>>>(srcp, dstp);

    // layer 1
    dim3 g1(NN/16, 4);
    k_node1<<<g1, 128>>>(x, Wq1,bq1, Wk1,bk1, Wv1,bv1, Ws1,bs1);
    dim3 gt1((NN+31)/32, 4);
    k_t1   <<<gt1, 256>>>(We1);
    k_attn1<<<(NN+7)/8, 256>>>(ef, We1);

    // layer 2
    k_node2<<<g1, 64>>>(Wq2,bq2, Wk2,bk2, Wv2,bv2, Ws2,bs2);
    k_t2   <<<(NN+31)/32, 256>>>(We2);
    k_attn2<<<(NN+7)/8, 256>>>(ef, We2, out);
}